// round 14
// baseline (speedup 1.0000x reference)
#include <cuda_runtime.h>
#include <cuda_bf16.h>
#include <mma.h>
using namespace nvcuda;

// Problem shape (fixed by dataset)
#define NMAX 50000
#define EMAX 600000
#define DIM  128
#define SCAN_TILE 2048 // elems per scan block (256 thr x 8)
#define SCAN_MAXB 64   // max scan blocks (50000/2048 -> 25)

// ---------------- device scratch (static allocation only) ----------------
__device__ float g_Q[NMAX * DIM];
__device__ float g_K[NMAX * DIM];
__device__ float g_V[NMAX * DIM];
__device__ float g_Whi[3][DIM * DIM];  // tf32-rounded weights (hi part)
__device__ float g_Wlo[3][DIM * DIM];  // tf32-rounded residual (lo part)
__device__ int   g_deg[NMAX + 8];      // zero-init at load; re-zeroed by scan_p3 each call
__device__ int   g_rowptr[NMAX + 1];
__device__ int   g_cursor[NMAX];
__device__ int   g_ecol[EMAX];         // cols permuted into CSR order
__device__ int   g_bsum[SCAN_MAXB];
__device__ int   g_boff[SCAN_MAXB];

// ---------------- tf32 helper ----------------
__device__ __forceinline__ float tf32_round(float x) {
    unsigned r;
    asm("cvt.rna.tf32.f32 %0, %1;" : "=r"(r) : "f"(x));
    return __uint_as_float(r);     // tf32 bit pattern is a valid fp32
}

// ---------------- kernel A: weight hi/lo split (once per launch) ----------------
// 3 * 128*128 = 49152 elems; grid 192 x 256.
__global__ void wprep_kernel(const float* __restrict__ wq,
                             const float* __restrict__ wk,
                             const float* __restrict__ wv) {
    int i = blockIdx.x * blockDim.x + threadIdx.x;
    if (i >= 3 * DIM * DIM) return;
    int m = i >> 14;            // /16384
    int o = i & 16383;
    const float* src = (m == 0) ? wq : (m == 1) ? wk : wv;
    float v  = src[o];
    float hi = tf32_round(v);
    g_Whi[m][o] = hi;
    g_Wlo[m][o] = tf32_round(v - hi);
}

// ---------------- kernel 1: QKV projection via wmma tf32 (3xTF32) ----------------
// Block: 256 threads = 8 warps, 16 rows. Warp w computes the 16x16 output tile
// at columns [16w, 16w+16) for Q, K and V. K-loop: 16 steps of k=8.
// Each product uses 3 mmas: Ahi*Bhi + Ahi*Blo + Alo*Bhi  (fp32-grade accuracy).
__global__ void __launch_bounds__(256) qkv_kernel(const float* __restrict__ emb, int n)
{
    const int w  = threadIdx.x >> 5;       // warp id = output ntile
    const int r0 = blockIdx.x * 16;
    if (r0 + 16 > n) return;               // full tiles only (N=50000 divisible by 16)

    wmma::fragment<wmma::accumulator, 16, 16, 8, float> accq, acck, accv;
    wmma::fill_fragment(accq, 0.f);
    wmma::fill_fragment(acck, 0.f);
    wmma::fill_fragment(accv, 0.f);

    wmma::fragment<wmma::matrix_a, 16, 16, 8, wmma::precision::tf32, wmma::row_major> araw, ahi, alo;
    wmma::fragment<wmma::matrix_b, 16, 16, 8, wmma::precision::tf32, wmma::row_major> bhi, blo;

    #pragma unroll
    for (int k0 = 0; k0 < DIM; k0 += 8) {
        wmma::load_matrix_sync(araw, emb + (size_t)r0 * DIM + k0, DIM);
        #pragma unroll
        for (int i = 0; i < araw.num_elements; i++) {
            float v  = araw.x[i];
            float hi = tf32_round(v);
            ahi.x[i] = hi;
            alo.x[i] = tf32_round(v - hi);
        }
        // Q
        wmma::load_matrix_sync(bhi, &g_Whi[0][k0 * DIM + w * 16], DIM);
        wmma::load_matrix_sync(blo, &g_Wlo[0][k0 * DIM + w * 16], DIM);
        wmma::mma_sync(accq, ahi, bhi, accq);
        wmma::mma_sync(accq, ahi, blo, accq);
        wmma::mma_sync(accq, alo, bhi, accq);
        // K
        wmma::load_matrix_sync(bhi, &g_Whi[1][k0 * DIM + w * 16], DIM);
        wmma::load_matrix_sync(blo, &g_Wlo[1][k0 * DIM + w * 16], DIM);
        wmma::mma_sync(acck, ahi, bhi, acck);
        wmma::mma_sync(acck, ahi, blo, acck);
        wmma::mma_sync(acck, alo, bhi, acck);
        // V
        wmma::load_matrix_sync(bhi, &g_Whi[2][k0 * DIM + w * 16], DIM);
        wmma::load_matrix_sync(blo, &g_Wlo[2][k0 * DIM + w * 16], DIM);
        wmma::mma_sync(accv, ahi, bhi, accv);
        wmma::mma_sync(accv, ahi, blo, accv);
        wmma::mma_sync(accv, alo, bhi, accv);
    }

    wmma::store_matrix_sync(g_Q + (size_t)r0 * DIM + w * 16, accq, DIM, wmma::mem_row_major);
    wmma::store_matrix_sync(g_K + (size_t)r0 * DIM + w * 16, acck, DIM, wmma::mem_row_major);
    wmma::store_matrix_sync(g_V + (size_t)r0 * DIM + w * 16, accv, DIM, wmma::mem_row_major);
}

// ---------------- kernel 1b: scalar remainder rows (only launched if n % 16) ----------------
__global__ void qkv_rem_kernel(const float* __restrict__ emb,
                               const float* __restrict__ wq,
                               const float* __restrict__ wk,
                               const float* __restrict__ wv,
                               int n, int r0) {
    int row = r0 + blockIdx.x;
    int j   = threadIdx.x;
    if (row >= n) return;
    float sq = 0.f, sk = 0.f, sv = 0.f;
    for (int k = 0; k < DIM; k++) {
        float e = emb[row * DIM + k];
        sq = fmaf(e, wq[k * DIM + j], sq);
        sk = fmaf(e, wk[k * DIM + j], sk);
        sv = fmaf(e, wv[k * DIM + j], sv);
    }
    g_Q[row * DIM + j] = sq;
    g_K[row * DIM + j] = sk;
    g_V[row * DIM + j] = sv;
}

// ---------------- kernel 2: degree histogram ----------------
__global__ void hist_kernel(const int* __restrict__ rows, int E) {
    int i = blockIdx.x * blockDim.x + threadIdx.x;
    if (i < E) atomicAdd(&g_deg[rows[i]], 1);
}

// ---------------- scan phase 1: per-block sums ----------------
__global__ void __launch_bounds__(256) scan_p1_kernel(int n) {
    __shared__ int ws[8];
    const int tid  = threadIdx.x;
    const int lane = tid & 31;
    const int wid  = tid >> 5;
    int base = blockIdx.x * SCAN_TILE + tid * 8;

    const int4* d4 = (const int4*)&g_deg[base];
    int s = 0;
    if (base < n) {
        int4 a = d4[0], b = d4[1];
        s = a.x + a.y + a.z + a.w + b.x + b.y + b.z + b.w;  // pad is zero
    }
    #pragma unroll
    for (int off = 16; off; off >>= 1) s += __shfl_xor_sync(0xffffffffu, s, off);
    if (lane == 0) ws[wid] = s;
    __syncthreads();
    if (tid == 0) {
        int t = 0;
        #pragma unroll
        for (int w = 0; w < 8; w++) t += ws[w];
        g_bsum[blockIdx.x] = t;
    }
}

// ---------------- scan phase 2: scan block sums (1 warp) ----------------
__global__ void scan_p2_kernel(int nblocks, int n) {
    int lane = threadIdx.x;
    __shared__ int carry;
    if (lane == 0) carry = 0;
    __syncwarp();
    for (int b0 = 0; b0 < nblocks; b0 += 32) {
        int i = b0 + lane;
        int v = (i < nblocks) ? g_bsum[i] : 0;
        int inc = v;
        #pragma unroll
        for (int off = 1; off < 32; off <<= 1) {
            int t = __shfl_up_sync(0xffffffffu, inc, off);
            if (lane >= off) inc += t;
        }
        int c = carry;
        if (i < nblocks) g_boff[i] = c + inc - v;
        if (lane == 31) carry = c + inc;
        __syncwarp();
    }
    if (lane == 0) g_rowptr[n] = carry;   // grand total
}

// ---------------- scan phase 3: rescan tiles, then re-zero deg for next call ----------------
__global__ void __launch_bounds__(256) scan_p3_kernel(int n) {
    __shared__ int warp_off[8];
    const int tid  = threadIdx.x;
    const int lane = tid & 31;
    const int wid  = tid >> 5;
    int base = blockIdx.x * SCAN_TILE + tid * 8;

    int v[8];
    int tot = 0;
    if (base < n) {
        int4* d4 = (int4*)&g_deg[base];
        int4 a = d4[0], b = d4[1];
        int d[8] = {a.x, a.y, a.z, a.w, b.x, b.y, b.z, b.w};
        #pragma unroll
        for (int i = 0; i < 8; i++) { v[i] = tot; tot += d[i]; }
        // leave deg zeroed so next graph replay's hist starts clean
        d4[0] = make_int4(0, 0, 0, 0);
        d4[1] = make_int4(0, 0, 0, 0);
    } else {
        #pragma unroll
        for (int i = 0; i < 8; i++) v[i] = 0;
    }

    int inc = tot;
    #pragma unroll
    for (int off = 1; off < 32; off <<= 1) {
        int t = __shfl_up_sync(0xffffffffu, inc, off);
        if (lane >= off) inc += t;
    }
    if (lane == 31) warp_off[wid] = inc;
    int texcl = inc - tot;
    __syncthreads();

    if (wid == 0 && lane < 8) {
        int w = warp_off[lane];
        int wi = w;
        #pragma unroll
        for (int off = 1; off < 8; off <<= 1) {
            int t = __shfl_up_sync(0x000000ffu, wi, off);
            if (lane >= off) wi += t;
        }
        warp_off[lane] = wi - w;
    }
    __syncthreads();

    int b = g_boff[blockIdx.x] + warp_off[wid] + texcl;
    #pragma unroll
    for (int i = 0; i < 8; i++) {
        int idx = base + i;
        if (idx < n) {
            int val = b + v[i];
            g_rowptr[idx] = val;
            g_cursor[idx] = val;
        }
    }
}

// ---------------- kernel 4: scatter col ids into CSR order ----------------
__global__ void scatter_kernel(const int* __restrict__ rows,
                               const int* __restrict__ cols, int E) {
    int i = blockIdx.x * blockDim.x + threadIdx.x;
    if (i < E) {
        int pos = atomicAdd(&g_cursor[rows[i]], 1);
        g_ecol[pos] = cols[i];
    }
}

// ---------------- kernel 5: fused single-pass segment-softmax attention ----------------
// One warp per destination node. Lane l holds dims [4l, 4l+4); head = l>>3.
// out = (sum_e ea_e * v_e) / (sum_e ea_e + 1e-8)  — norm factored out of the sum.
__global__ void __launch_bounds__(256) attn_kernel(float* __restrict__ out, int n)
{
    int gw   = (blockIdx.x * blockDim.x + threadIdx.x) >> 5;
    int lane = threadIdx.x & 31;
    if (gw >= n) return;

    const float4* Q4 = (const float4*)g_Q;
    const float4* K4 = (const float4*)g_K;
    const float4* V4 = (const float4*)g_V;

    float4 qv = Q4[gw * 32 + lane];
    int beg = g_rowptr[gw];
    int end = g_rowptr[gw + 1];

    float nsum = 0.f;
    float4 acc = make_float4(0.f, 0.f, 0.f, 0.f);
    for (int idx = beg; idx < end; idx++) {
        int c = g_ecol[idx];                      // sequential read, CSR order
        float4 kv = K4[c * 32 + lane];            // two independent row gathers
        float4 vv = V4[c * 32 + lane];
        float p = fmaf(qv.x, kv.x, fmaf(qv.y, kv.y, fmaf(qv.z, kv.z, qv.w * kv.w)));
        p += __shfl_xor_sync(0xffffffffu, p, 1);
        p += __shfl_xor_sync(0xffffffffu, p, 2);
        p += __shfl_xor_sync(0xffffffffu, p, 4);  // full head dot in all 8 lanes of group
        float a  = fminf(fmaxf(p, -10.f), 10.f);
        float ea = __expf(a);
        nsum += ea;
        acc.x = fmaf(ea, vv.x, acc.x);
        acc.y = fmaf(ea, vv.y, acc.y);
        acc.z = fmaf(ea, vv.z, acc.z);
        acc.w = fmaf(ea, vv.w, acc.w);
    }
    float inv = 1.f / (nsum + 1e-8f);
    acc.x *= inv; acc.y *= inv; acc.z *= inv; acc.w *= inv;
    ((float4*)out)[gw * 32 + lane] = acc;
}

// ---------------- launch ----------------
// Order chosen so the profiled launch (index 3) is qkv_kernel.
extern "C" void kernel_launch(void* const* d_in, const int* in_sizes, int n_in,
                              void* d_out, int out_size) {
    const float* emb  = (const float*)d_in[0];
    const float* qW   = (const float*)d_in[1];
    const float* kW   = (const float*)d_in[2];
    const float* vW   = (const float*)d_in[3];
    const int*   rows = (const int*)d_in[4];
    const int*   cols = (const int*)d_in[5];
    float*       out  = (float*)d_out;

    const int N = in_sizes[0] / DIM;   // 50000
    const int E = in_sizes[4];         // 600000
    const int nsb   = (N + SCAN_TILE - 1) / SCAN_TILE;   // 25
    const int ntile = N / 16;          // full 16-row tiles (3125)
    const int nrem  = N - ntile * 16;  // remainder rows (0 for this dataset)

    hist_kernel<<<(E + 255) / 256, 256>>>(rows, E);              // 0
    scan_p1_kernel<<<nsb, 256>>>(N);                             // 1
    wprep_kernel<<<192, 256>>>(qW, kW, vW);                      // 2
    qkv_kernel<<<ntile, 256>>>(emb, N);                          // 3  <- profiled
    scan_p2_kernel<<<1, 32>>>(nsb, N);                           // 4
    scan_p3_kernel<<<nsb, 256>>>(N);                             // 5
    scatter_kernel<<<(E + 255) / 256, 256>>>(rows, cols, E);     // 6
    if (nrem > 0)
        qkv_rem_kernel<<<nrem, DIM>>>(emb, qW, kW, vW, N, ntile * 16);
    attn_kernel<<<(N + 7) / 8, 256>>>(out, N);                   // last
}

// round 15
// speedup vs baseline: 1.1624x; 1.1624x over previous
#include <cuda_runtime.h>
#include <cuda_bf16.h>

// Problem shape (fixed by dataset)
#define NMAX 50000
#define EMAX 600000
#define DIM  128
#define GR   16        // rows per block in QKV GEMM (8+8 across thread halves)
#define SCAN_TILE 2048 // elems per scan block (256 thr x 8)
#define SCAN_MAXB 32   // max scan blocks (needs N <= 65536; 50000/2048 -> 25)

// ---------------- device scratch (static allocation only) ----------------
__device__ float g_Q[NMAX * DIM];
__device__ float g_K[NMAX * DIM];
__device__ float g_V[NMAX * DIM];
__device__ unsigned long long g_Wdup[3][DIM * DIM];  // {w,w} duplicated pairs
__device__ int   g_deg[NMAX + 8];      // zero-init at load; re-zeroed by scan_p3 each call
__device__ int   g_rowptr[NMAX + 1];
__device__ int   g_cursor[NMAX];
__device__ int   g_ecol[EMAX];         // cols permuted into CSR order
__device__ int   g_bsum[SCAN_MAXB];
__device__ int   g_boff[SCAN_MAXB];
__device__ unsigned g_p1ticket;        // last-block ticket; reset to 0 each use

// ---------------- packed f32x2 helpers ----------------
__device__ __forceinline__ void ffma2(unsigned long long& acc,
                                      unsigned long long a,
                                      unsigned long long b) {
    asm("fma.rn.f32x2 %0, %1, %2, %0;" : "+l"(acc) : "l"(a), "l"(b));
}
__device__ __forceinline__ void unpack2(unsigned long long v, float& lo, float& hi) {
    unsigned a, b;
    asm("mov.b64 {%0, %1}, %2;" : "=r"(a), "=r"(b) : "l"(v));
    lo = __uint_as_float(a);
    hi = __uint_as_float(b);
}

// ---------------- kernel A: duplicate weights into f32x2 pairs (once per launch) ----------------
__global__ void wdup_kernel(const float* __restrict__ wq,
                            const float* __restrict__ wk,
                            const float* __restrict__ wv) {
    int i = blockIdx.x * blockDim.x + threadIdx.x;
    if (i >= 3 * DIM * DIM) return;
    int m = i >> 14;            // /16384
    int o = i & 16383;
    const float* src = (m == 0) ? wq : (m == 1) ? wk : wv;
    unsigned u = __float_as_uint(src[o]);
    unsigned long long d;
    asm("mov.b64 %0, {%1, %1};" : "=l"(d) : "r"(u));
    g_Wdup[m][o] = d;
}

// ---------------- kernel 1: fused Q/K/V projection (row-packed f32x2) ----------------
// 256 threads: j = tid&127 (output column), half = tid>>7 owns 8 of the 16 rows.
// Weight multiplier comes pre-duplicated from g_Wdup -> one coalesced LDG.64
// per matrix per k (no broadcast movs). 12 FFMA2 per ~17 inst -> ~71% issue eff.
__global__ void __launch_bounds__(256) qkv_kernel(
    const float* __restrict__ emb, int n)
{
    __shared__ __align__(16) float et[DIM][20];   // k-major; 80B row stride (16B aligned)
    const int j    = threadIdx.x & 127;           // output column 0..127
    const int half = threadIdx.x >> 7;            // 0 or 1
    const int rb   = half * 8;                    // first row of this half within tile
    const int r0   = blockIdx.x * GR;

    // thread loads its half's 8 rows for k=j (k-major tile, coalesced per row)
    #pragma unroll
    for (int r = 0; r < 8; r++) {
        int row = r0 + rb + r;
        et[j][rb + r] = (row < n) ? emb[row * DIM + j] : 0.f;
    }
    __syncthreads();

    const unsigned long long* wq2 = &g_Wdup[0][j];
    const unsigned long long* wk2 = &g_Wdup[1][j];
    const unsigned long long* wv2 = &g_Wdup[2][j];

    // 4 packed accumulators per matrix: pair i = rows (rb+2i, rb+2i+1)
    unsigned long long aq[4], ak[4], av[4];
    #pragma unroll
    for (int i = 0; i < 4; i++) { aq[i] = 0ull; ak[i] = 0ull; av[i] = 0ull; }

    #pragma unroll 4
    for (int k = 0; k < DIM; k++) {
        unsigned long long q2 = __ldg(&wq2[k * DIM]);   // {w,w} pair, coalesced LDG.64
        unsigned long long k2 = __ldg(&wk2[k * DIM]);
        unsigned long long v2 = __ldg(&wv2[k * DIM]);
        const ulonglong2* ep = (const ulonglong2*)(&et[k][rb]);  // 16B aligned (80k+32h)
        #pragma unroll
        for (int p = 0; p < 2; p++) {
            ulonglong2 e2 = ep[p];    // 4 rows packed pairwise; warp-broadcast read
            ffma2(aq[2 * p],     e2.x, q2);
            ffma2(aq[2 * p + 1], e2.y, q2);
            ffma2(ak[2 * p],     e2.x, k2);
            ffma2(ak[2 * p + 1], e2.y, k2);
            ffma2(av[2 * p],     e2.x, v2);
            ffma2(av[2 * p + 1], e2.y, v2);
        }
    }

    #pragma unroll
    for (int i = 0; i < 4; i++) {
        float qlo, qhi, klo, khi, vlo, vhi;
        unpack2(aq[i], qlo, qhi);
        unpack2(ak[i], klo, khi);
        unpack2(av[i], vlo, vhi);
        int row = r0 + rb + 2 * i;
        if (row < n) {
            g_Q[row * DIM + j] = qlo;
            g_K[row * DIM + j] = klo;
            g_V[row * DIM + j] = vlo;
        }
        if (row + 1 < n) {
            g_Q[(row + 1) * DIM + j] = qhi;
            g_K[(row + 1) * DIM + j] = khi;
            g_V[(row + 1) * DIM + j] = vhi;
        }
    }
}

// ---------------- kernel 2: degree histogram ----------------
__global__ void hist_kernel(const int* __restrict__ rows, int E) {
    int i = blockIdx.x * blockDim.x + threadIdx.x;
    if (i < E) atomicAdd(&g_deg[rows[i]], 1);
}

// ---------------- scan phase 1+2 fused: per-block sums, last block scans them ----------------
__global__ void __launch_bounds__(256) scan_p12_kernel(int n, int nblocks) {
    __shared__ int ws[8];
    __shared__ int s_last;
    const int tid  = threadIdx.x;
    const int lane = tid & 31;
    const int wid  = tid >> 5;
    int base = blockIdx.x * SCAN_TILE + tid * 8;

    const int4* d4 = (const int4*)&g_deg[base];
    int s = 0;
    if (base < n) {
        int4 a = d4[0], b = d4[1];
        s = a.x + a.y + a.z + a.w + b.x + b.y + b.z + b.w;  // pad is zero
    }
    #pragma unroll
    for (int off = 16; off; off >>= 1) s += __shfl_xor_sync(0xffffffffu, s, off);
    if (lane == 0) ws[wid] = s;
    __syncthreads();
    if (tid == 0) {
        int t = 0;
        #pragma unroll
        for (int w = 0; w < 8; w++) t += ws[w];
        g_bsum[blockIdx.x] = t;
        __threadfence();                                   // bsum visible before ticket
        unsigned old = atomicAdd(&g_p1ticket, 1u);
        s_last = (old == (unsigned)(nblocks - 1)) ? 1 : 0;
    }
    __syncthreads();

    if (s_last && wid == 0) {   // last arriving block: scan the block sums (nblocks <= 32)
        int v = (lane < nblocks) ? g_bsum[lane] : 0;
        int inc = v;
        #pragma unroll
        for (int off = 1; off < 32; off <<= 1) {
            int t = __shfl_up_sync(0xffffffffu, inc, off);
            if (lane >= off) inc += t;
        }
        if (lane < nblocks) g_boff[lane] = inc - v;        // exclusive offsets
        if (lane == 31) g_rowptr[n] = inc;                 // grand total
        if (lane == 0) g_p1ticket = 0;                     // reset for next replay
    }
}

// ---------------- scan phase 3: rescan tiles, then re-zero deg for next call ----------------
__global__ void __launch_bounds__(256) scan_p3_kernel(int n) {
    __shared__ int warp_off[8];
    const int tid  = threadIdx.x;
    const int lane = tid & 31;
    const int wid  = tid >> 5;
    int base = blockIdx.x * SCAN_TILE + tid * 8;

    int v[8];
    int tot = 0;
    if (base < n) {
        int4* d4 = (int4*)&g_deg[base];
        int4 a = d4[0], b = d4[1];
        int d[8] = {a.x, a.y, a.z, a.w, b.x, b.y, b.z, b.w};
        #pragma unroll
        for (int i = 0; i < 8; i++) { v[i] = tot; tot += d[i]; }
        // leave deg zeroed so next graph replay's hist starts clean
        d4[0] = make_int4(0, 0, 0, 0);
        d4[1] = make_int4(0, 0, 0, 0);
    } else {
        #pragma unroll
        for (int i = 0; i < 8; i++) v[i] = 0;
    }

    int inc = tot;
    #pragma unroll
    for (int off = 1; off < 32; off <<= 1) {
        int t = __shfl_up_sync(0xffffffffu, inc, off);
        if (lane >= off) inc += t;
    }
    if (lane == 31) warp_off[wid] = inc;
    int texcl = inc - tot;
    __syncthreads();

    if (wid == 0 && lane < 8) {
        int w = warp_off[lane];
        int wi = w;
        #pragma unroll
        for (int off = 1; off < 8; off <<= 1) {
            int t = __shfl_up_sync(0x000000ffu, wi, off);
            if (lane >= off) wi += t;
        }
        warp_off[lane] = wi - w;
    }
    __syncthreads();

    int b = g_boff[blockIdx.x] + warp_off[wid] + texcl;
    #pragma unroll
    for (int i = 0; i < 8; i++) {
        int idx = base + i;
        if (idx < n) {
            int val = b + v[i];
            g_rowptr[idx] = val;
            g_cursor[idx] = val;
        }
    }
}

// ---------------- kernel 4: scatter col ids into CSR order ----------------
__global__ void scatter_kernel(const int* __restrict__ rows,
                               const int* __restrict__ cols, int E) {
    int i = blockIdx.x * blockDim.x + threadIdx.x;
    if (i < E) {
        int pos = atomicAdd(&g_cursor[rows[i]], 1);
        g_ecol[pos] = cols[i];
    }
}

// ---------------- kernel 5: fused single-pass segment-softmax attention ----------------
// One warp per destination node. Lane l holds dims [4l, 4l+4); head = l>>3.
// out = (sum_e ea_e * v_e) / (sum_e ea_e + 1e-8)  — norm factored out of the sum.
__global__ void __launch_bounds__(256) attn_kernel(float* __restrict__ out, int n)
{
    int gw   = (blockIdx.x * blockDim.x + threadIdx.x) >> 5;
    int lane = threadIdx.x & 31;
    if (gw >= n) return;

    const float4* Q4 = (const float4*)g_Q;
    const float4* K4 = (const float4*)g_K;
    const float4* V4 = (const float4*)g_V;

    float4 qv = Q4[gw * 32 + lane];
    int beg = g_rowptr[gw];
    int end = g_rowptr[gw + 1];

    float nsum = 0.f;
    float4 acc = make_float4(0.f, 0.f, 0.f, 0.f);
    for (int idx = beg; idx < end; idx++) {
        int c = g_ecol[idx];                      // sequential read, CSR order
        float4 kv = K4[c * 32 + lane];            // two independent row gathers
        float4 vv = V4[c * 32 + lane];
        float p = fmaf(qv.x, kv.x, fmaf(qv.y, kv.y, fmaf(qv.z, kv.z, qv.w * kv.w)));
        p += __shfl_xor_sync(0xffffffffu, p, 1);
        p += __shfl_xor_sync(0xffffffffu, p, 2);
        p += __shfl_xor_sync(0xffffffffu, p, 4);  // full head dot in all 8 lanes of group
        float a  = fminf(fmaxf(p, -10.f), 10.f);
        float ea = __expf(a);
        nsum += ea;
        acc.x = fmaf(ea, vv.x, acc.x);
        acc.y = fmaf(ea, vv.y, acc.y);
        acc.z = fmaf(ea, vv.z, acc.z);
        acc.w = fmaf(ea, vv.w, acc.w);
    }
    float inv = 1.f / (nsum + 1e-8f);
    acc.x *= inv; acc.y *= inv; acc.z *= inv; acc.w *= inv;
    ((float4*)out)[gw * 32 + lane] = acc;
}

// ---------------- launch ----------------
// Order chosen so the profiled launch (index 3) is qkv_kernel.
extern "C" void kernel_launch(void* const* d_in, const int* in_sizes, int n_in,
                              void* d_out, int out_size) {
    const float* emb  = (const float*)d_in[0];
    const float* qW   = (const float*)d_in[1];
    const float* kW   = (const float*)d_in[2];
    const float* vW   = (const float*)d_in[3];
    const int*   rows = (const int*)d_in[4];
    const int*   cols = (const int*)d_in[5];
    float*       out  = (float*)d_out;

    const int N = in_sizes[0] / DIM;   // 50000
    const int E = in_sizes[4];         // 600000
    const int nsb = (N + SCAN_TILE - 1) / SCAN_TILE;   // 25 (<= SCAN_MAXB)

    hist_kernel<<<(E + 255) / 256, 256>>>(rows, E);              // 0
    wdup_kernel<<<192, 256>>>(qW, kW, vW);                       // 1
    scan_p12_kernel<<<nsb, 256>>>(N, nsb);                       // 2
    qkv_kernel<<<(N + GR - 1) / GR, 256>>>(emb, N);              // 3  <- profiled
    scan_p3_kernel<<<nsb, 256>>>(N);                             // 4
    scatter_kernel<<<(E + 255) / 256, 256>>>(rows, cols, E);     // 5
    attn_kernel<<<(N + 7) / 8, 256>>>(out, N);                   // 6
}

// round 16
// speedup vs baseline: 1.4096x; 1.2127x over previous
#include <cuda_runtime.h>
#include <cuda_bf16.h>

// Problem shape (fixed by dataset)
#define NMAX 50000
#define EMAX 600000
#define DIM  128
#define GR   16        // rows per block in QKV GEMM (8+8 across thread halves)
#define SCAN_TILE 2048 // elems per scan block (256 thr x 8)
#define SCAN_MAXB 32   // max scan blocks (needs N <= 65536; 50000/2048 -> 25)

// ---------------- device scratch (static allocation only) ----------------
__device__ float g_Q[NMAX * DIM];
__device__ float g_K[NMAX * DIM];
__device__ float g_V[NMAX * DIM];
__device__ int   g_deg[NMAX + 8];      // zero-init at load; re-zeroed by scan_p3 each call
__device__ int   g_rowptr[NMAX + 1];
__device__ int   g_cursor[NMAX];
__device__ int   g_ecol[EMAX];         // cols permuted into CSR order
__device__ int   g_bsum[SCAN_MAXB];
__device__ int   g_boff[SCAN_MAXB];
__device__ unsigned g_p1ticket;        // last-block ticket; reset to 0 each use

// ---------------- packed f32x2 helpers ----------------
__device__ __forceinline__ void ffma2(unsigned long long& acc,
                                      unsigned long long a,
                                      unsigned long long b) {
    asm("fma.rn.f32x2 %0, %1, %2, %0;" : "+l"(acc) : "l"(a), "l"(b));
}
__device__ __forceinline__ unsigned long long bcast2(float x) {
    unsigned long long r;
    unsigned u = __float_as_uint(x);
    asm("mov.b64 %0, {%1, %1};" : "=l"(r) : "r"(u));
    return r;
}
__device__ __forceinline__ void unpack2(unsigned long long v, float& lo, float& hi) {
    unsigned a, b;
    asm("mov.b64 {%0, %1}, %2;" : "=r"(a), "=r"(b) : "l"(v));
    lo = __uint_as_float(a);
    hi = __uint_as_float(b);
}

// ---------------- kernel 1: fused Q/K/V projection + degree histogram ----------------
// Blocks [0, nqkv): R11-proven qkv. 256 threads: j = tid&127 (output column),
// half = tid>>7 owns 8 of the 16 rows. Coalesced scalar weight LDGs (192KB table
// stays L1-resident), broadcast movs, 4 packed f32x2 accumulators per matrix.
// Blocks [nqkv, nqkv+nhist): degree histogram over the edge rows array.
__global__ void __launch_bounds__(256) qkvhist_kernel(
    const float* __restrict__ emb,
    const float* __restrict__ wq,
    const float* __restrict__ wk,
    const float* __restrict__ wv,
    const int*   __restrict__ rows,
    int n, int nqkv, int E)
{
    if (blockIdx.x >= (unsigned)nqkv) {
        // ---- histogram part ----
        int i = (blockIdx.x - nqkv) * blockDim.x + threadIdx.x;
        if (i < E) atomicAdd(&g_deg[rows[i]], 1);
        return;
    }

    // ---- qkv part (exact R11 layout) ----
    __shared__ __align__(16) float et[DIM][20];   // k-major; 80B row stride (16B aligned)
    const int j    = threadIdx.x & 127;           // output column 0..127
    const int half = threadIdx.x >> 7;            // 0 or 1
    const int rb   = half * 8;                    // first row of this half within tile
    const int r0   = blockIdx.x * GR;

    #pragma unroll
    for (int r = 0; r < 8; r++) {
        int row = r0 + rb + r;
        et[j][rb + r] = (row < n) ? emb[row * DIM + j] : 0.f;
    }
    __syncthreads();

    unsigned long long aq[4], ak[4], av[4];
    #pragma unroll
    for (int i = 0; i < 4; i++) { aq[i] = 0ull; ak[i] = 0ull; av[i] = 0ull; }

    #pragma unroll 4
    for (int k = 0; k < DIM; k++) {
        unsigned long long q2 = bcast2(__ldg(&wq[k * DIM + j]));
        unsigned long long k2 = bcast2(__ldg(&wk[k * DIM + j]));
        unsigned long long v2 = bcast2(__ldg(&wv[k * DIM + j]));
        const ulonglong2* ep = (const ulonglong2*)(&et[k][rb]);  // 16B aligned (80k+32h)
        #pragma unroll
        for (int p = 0; p < 2; p++) {
            ulonglong2 e2 = ep[p];    // 4 rows packed pairwise; warp-broadcast read
            ffma2(aq[2 * p],     e2.x, q2);
            ffma2(aq[2 * p + 1], e2.y, q2);
            ffma2(ak[2 * p],     e2.x, k2);
            ffma2(ak[2 * p + 1], e2.y, k2);
            ffma2(av[2 * p],     e2.x, v2);
            ffma2(av[2 * p + 1], e2.y, v2);
        }
    }

    #pragma unroll
    for (int i = 0; i < 4; i++) {
        float qlo, qhi, klo, khi, vlo, vhi;
        unpack2(aq[i], qlo, qhi);
        unpack2(ak[i], klo, khi);
        unpack2(av[i], vlo, vhi);
        int row = r0 + rb + 2 * i;
        if (row < n) {
            g_Q[row * DIM + j] = qlo;
            g_K[row * DIM + j] = klo;
            g_V[row * DIM + j] = vlo;
        }
        if (row + 1 < n) {
            g_Q[(row + 1) * DIM + j] = qhi;
            g_K[(row + 1) * DIM + j] = khi;
            g_V[(row + 1) * DIM + j] = vhi;
        }
    }
}

// ---------------- scan phase 1+2 fused: per-block sums, last block scans them ----------------
__global__ void __launch_bounds__(256) scan_p12_kernel(int n, int nblocks) {
    __shared__ int ws[8];
    __shared__ int s_last;
    const int tid  = threadIdx.x;
    const int lane = tid & 31;
    const int wid  = tid >> 5;
    int base = blockIdx.x * SCAN_TILE + tid * 8;

    const int4* d4 = (const int4*)&g_deg[base];
    int s = 0;
    if (base < n) {
        int4 a = d4[0], b = d4[1];
        s = a.x + a.y + a.z + a.w + b.x + b.y + b.z + b.w;  // pad is zero
    }
    #pragma unroll
    for (int off = 16; off; off >>= 1) s += __shfl_xor_sync(0xffffffffu, s, off);
    if (lane == 0) ws[wid] = s;
    __syncthreads();
    if (tid == 0) {
        int t = 0;
        #pragma unroll
        for (int w = 0; w < 8; w++) t += ws[w];
        g_bsum[blockIdx.x] = t;
        __threadfence();                                   // bsum visible before ticket
        unsigned old = atomicAdd(&g_p1ticket, 1u);
        s_last = (old == (unsigned)(nblocks - 1)) ? 1 : 0;
    }
    __syncthreads();

    if (s_last && wid == 0) {   // last arriving block: scan the block sums (nblocks <= 32)
        int v = (lane < nblocks) ? g_bsum[lane] : 0;
        int inc = v;
        #pragma unroll
        for (int off = 1; off < 32; off <<= 1) {
            int t = __shfl_up_sync(0xffffffffu, inc, off);
            if (lane >= off) inc += t;
        }
        if (lane < nblocks) g_boff[lane] = inc - v;        // exclusive offsets
        if (lane == 31) g_rowptr[n] = inc;                 // grand total
        if (lane == 0) g_p1ticket = 0;                     // reset for next replay
    }
}

// ---------------- scan phase 3: rescan tiles, then re-zero deg for next call ----------------
__global__ void __launch_bounds__(256) scan_p3_kernel(int n) {
    __shared__ int warp_off[8];
    const int tid  = threadIdx.x;
    const int lane = tid & 31;
    const int wid  = tid >> 5;
    int base = blockIdx.x * SCAN_TILE + tid * 8;

    int v[8];
    int tot = 0;
    if (base < n) {
        int4* d4 = (int4*)&g_deg[base];
        int4 a = d4[0], b = d4[1];
        int d[8] = {a.x, a.y, a.z, a.w, b.x, b.y, b.z, b.w};
        #pragma unroll
        for (int i = 0; i < 8; i++) { v[i] = tot; tot += d[i]; }
        // leave deg zeroed so next graph replay's hist starts clean
        d4[0] = make_int4(0, 0, 0, 0);
        d4[1] = make_int4(0, 0, 0, 0);
    } else {
        #pragma unroll
        for (int i = 0; i < 8; i++) v[i] = 0;
    }

    int inc = tot;
    #pragma unroll
    for (int off = 1; off < 32; off <<= 1) {
        int t = __shfl_up_sync(0xffffffffu, inc, off);
        if (lane >= off) inc += t;
    }
    if (lane == 31) warp_off[wid] = inc;
    int texcl = inc - tot;
    __syncthreads();

    if (wid == 0 && lane < 8) {
        int w = warp_off[lane];
        int wi = w;
        #pragma unroll
        for (int off = 1; off < 8; off <<= 1) {
            int t = __shfl_up_sync(0x000000ffu, wi, off);
            if (lane >= off) wi += t;
        }
        warp_off[lane] = wi - w;
    }
    __syncthreads();

    int b = g_boff[blockIdx.x] + warp_off[wid] + texcl;
    #pragma unroll
    for (int i = 0; i < 8; i++) {
        int idx = base + i;
        if (idx < n) {
            int val = b + v[i];
            g_rowptr[idx] = val;
            g_cursor[idx] = val;
        }
    }
}

// ---------------- kernel 4: scatter col ids into CSR order ----------------
__global__ void scatter_kernel(const int* __restrict__ rows,
                               const int* __restrict__ cols, int E) {
    int i = blockIdx.x * blockDim.x + threadIdx.x;
    if (i < E) {
        int pos = atomicAdd(&g_cursor[rows[i]], 1);
        g_ecol[pos] = cols[i];
    }
}

// ---------------- kernel 5: fused single-pass segment-softmax attention ----------------
// One warp per destination node. Lane l holds dims [4l, 4l+4); head = l>>3.
// out = (sum_e ea_e * v_e) / (sum_e ea_e + 1e-8)  — norm factored out of the sum.
__global__ void __launch_bounds__(256) attn_kernel(float* __restrict__ out, int n)
{
    int gw   = (blockIdx.x * blockDim.x + threadIdx.x) >> 5;
    int lane = threadIdx.x & 31;
    if (gw >= n) return;

    const float4* Q4 = (const float4*)g_Q;
    const float4* K4 = (const float4*)g_K;
    const float4* V4 = (const float4*)g_V;

    float4 qv = Q4[gw * 32 + lane];
    int beg = g_rowptr[gw];
    int end = g_rowptr[gw + 1];

    float nsum = 0.f;
    float4 acc = make_float4(0.f, 0.f, 0.f, 0.f);
    for (int idx = beg; idx < end; idx++) {
        int c = g_ecol[idx];                      // sequential read, CSR order
        float4 kv = K4[c * 32 + lane];            // two independent row gathers
        float4 vv = V4[c * 32 + lane];
        float p = fmaf(qv.x, kv.x, fmaf(qv.y, kv.y, fmaf(qv.z, kv.z, qv.w * kv.w)));
        p += __shfl_xor_sync(0xffffffffu, p, 1);
        p += __shfl_xor_sync(0xffffffffu, p, 2);
        p += __shfl_xor_sync(0xffffffffu, p, 4);  // full head dot in all 8 lanes of group
        float a  = fminf(fmaxf(p, -10.f), 10.f);
        float ea = __expf(a);
        nsum += ea;
        acc.x = fmaf(ea, vv.x, acc.x);
        acc.y = fmaf(ea, vv.y, acc.y);
        acc.z = fmaf(ea, vv.z, acc.z);
        acc.w = fmaf(ea, vv.w, acc.w);
    }
    float inv = 1.f / (nsum + 1e-8f);
    acc.x *= inv; acc.y *= inv; acc.z *= inv; acc.w *= inv;
    ((float4*)out)[gw * 32 + lane] = acc;
}

// ---------------- launch ----------------
extern "C" void kernel_launch(void* const* d_in, const int* in_sizes, int n_in,
                              void* d_out, int out_size) {
    const float* emb  = (const float*)d_in[0];
    const float* qW   = (const float*)d_in[1];
    const float* kW   = (const float*)d_in[2];
    const float* vW   = (const float*)d_in[3];
    const int*   rows = (const int*)d_in[4];
    const int*   cols = (const int*)d_in[5];
    float*       out  = (float*)d_out;

    const int N = in_sizes[0] / DIM;   // 50000
    const int E = in_sizes[4];         // 600000
    const int nsb   = (N + SCAN_TILE - 1) / SCAN_TILE;   // 25 (<= SCAN_MAXB)
    const int nqkv  = (N + GR - 1) / GR;                 // 3125
    const int nhist = (E + 255) / 256;                   // 2344

    qkvhist_kernel<<<nqkv + nhist, 256>>>(emb, qW, kW, vW, rows, N, nqkv, E); // 0
    scan_p12_kernel<<<nsb, 256>>>(N, nsb);                                    // 1
    scan_p3_kernel<<<nsb, 256>>>(N);                                          // 2
    scatter_kernel<<<(E + 255) / 256, 256>>>(rows, cols, E);                  // 3
    attn_kernel<<<(N + 7) / 8, 256>>>(out, N);                                // 4
}

// round 17
// speedup vs baseline: 1.4180x; 1.0060x over previous
#include <cuda_runtime.h>
#include <cuda_bf16.h>

// Problem shape (fixed by dataset)
#define NMAX 50000
#define EMAX 600000
#define DIM  128
#define GR   16        // rows per block in QKV GEMM (8+8 across thread halves)
#define SCAN_TILE 2048 // elems per scan block (256 thr x 8)
#define SCAN_MAXB 32   // max scan blocks (needs N <= 65536; 50000/2048 -> 25)

// ---------------- device scratch (static allocation only) ----------------
__device__ float g_Q[NMAX * DIM];
__device__ float g_K[NMAX * DIM];
__device__ float g_V[NMAX * DIM];
__device__ int   g_deg[NMAX + 8];      // zero-init at load; re-zeroed by scan each call
__device__ int   g_rowptr[NMAX + 1];
__device__ int   g_cursor[NMAX];
__device__ int   g_ecol[EMAX];         // cols permuted into CSR order
__device__ int   g_bsum[SCAN_MAXB];
__device__ int   g_boff[SCAN_MAXB];
__device__ unsigned g_ticket1;         // arrival ticket  (reset each call)
__device__ unsigned g_ticket2;         // departure ticket (reset each call)
__device__ unsigned g_scanflag;        // boff-ready flag (reset each call)

// ---------------- packed f32x2 helpers ----------------
__device__ __forceinline__ void ffma2(unsigned long long& acc,
                                      unsigned long long a,
                                      unsigned long long b) {
    asm("fma.rn.f32x2 %0, %1, %2, %0;" : "+l"(acc) : "l"(a), "l"(b));
}
__device__ __forceinline__ unsigned long long bcast2(float x) {
    unsigned long long r;
    unsigned u = __float_as_uint(x);
    asm("mov.b64 %0, {%1, %1};" : "=l"(r) : "r"(u));
    return r;
}
__device__ __forceinline__ void unpack2(unsigned long long v, float& lo, float& hi) {
    unsigned a, b;
    asm("mov.b64 {%0, %1}, %2;" : "=r"(a), "=r"(b) : "l"(v));
    lo = __uint_as_float(a);
    hi = __uint_as_float(b);
}

// ---------------- kernel 1: fused Q/K/V projection + degree histogram ----------------
// Blocks [0, nqkv): R11-proven qkv. Blocks [nqkv, ...): degree histogram.
__global__ void __launch_bounds__(256) qkvhist_kernel(
    const float* __restrict__ emb,
    const float* __restrict__ wq,
    const float* __restrict__ wk,
    const float* __restrict__ wv,
    const int*   __restrict__ rows,
    int n, int nqkv, int E)
{
    if (blockIdx.x >= (unsigned)nqkv) {
        int i = (blockIdx.x - nqkv) * blockDim.x + threadIdx.x;
        if (i < E) atomicAdd(&g_deg[rows[i]], 1);
        return;
    }

    __shared__ __align__(16) float et[DIM][20];   // k-major; 80B row stride (16B aligned)
    const int j    = threadIdx.x & 127;           // output column 0..127
    const int half = threadIdx.x >> 7;            // 0 or 1
    const int rb   = half * 8;                    // first row of this half within tile
    const int r0   = blockIdx.x * GR;

    #pragma unroll
    for (int r = 0; r < 8; r++) {
        int row = r0 + rb + r;
        et[j][rb + r] = (row < n) ? emb[row * DIM + j] : 0.f;
    }
    __syncthreads();

    unsigned long long aq[4], ak[4], av[4];
    #pragma unroll
    for (int i = 0; i < 4; i++) { aq[i] = 0ull; ak[i] = 0ull; av[i] = 0ull; }

    #pragma unroll 4
    for (int k = 0; k < DIM; k++) {
        unsigned long long q2 = bcast2(__ldg(&wq[k * DIM + j]));
        unsigned long long k2 = bcast2(__ldg(&wk[k * DIM + j]));
        unsigned long long v2 = bcast2(__ldg(&wv[k * DIM + j]));
        const ulonglong2* ep = (const ulonglong2*)(&et[k][rb]);  // 16B aligned
        #pragma unroll
        for (int p = 0; p < 2; p++) {
            ulonglong2 e2 = ep[p];
            ffma2(aq[2 * p],     e2.x, q2);
            ffma2(aq[2 * p + 1], e2.y, q2);
            ffma2(ak[2 * p],     e2.x, k2);
            ffma2(ak[2 * p + 1], e2.y, k2);
            ffma2(av[2 * p],     e2.x, v2);
            ffma2(av[2 * p + 1], e2.y, v2);
        }
    }

    #pragma unroll
    for (int i = 0; i < 4; i++) {
        float qlo, qhi, klo, khi, vlo, vhi;
        unpack2(aq[i], qlo, qhi);
        unpack2(ak[i], klo, khi);
        unpack2(av[i], vlo, vhi);
        int row = r0 + rb + 2 * i;
        if (row < n) {
            g_Q[row * DIM + j] = qlo;
            g_K[row * DIM + j] = klo;
            g_V[row * DIM + j] = vlo;
        }
        if (row + 1 < n) {
            g_Q[(row + 1) * DIM + j] = qhi;
            g_K[(row + 1) * DIM + j] = khi;
            g_V[(row + 1) * DIM + j] = vhi;
        }
    }
}

// ---------------- kernel 2: fully fused exclusive scan (25 co-resident blocks) ----------------
// Each block: tile local prefix + block sum -> publish -> last-arriving block
// scans the block sums and raises flag -> all blocks spin, then write
// rowptr/cursor and re-zero deg. Tickets/flag self-reset for graph replay.
__global__ void __launch_bounds__(256) scan_kernel(int n, int nblocks) {
    __shared__ int warp_off[8];
    __shared__ int s_tot;
    __shared__ int s_last;
    const int tid  = threadIdx.x;
    const int lane = tid & 31;
    const int wid  = tid >> 5;
    int base = blockIdx.x * SCAN_TILE + tid * 8;

    // --- local prefix over this thread's 8 elements; zero deg behind us ---
    int v[8];
    int tot = 0;
    if (base < n) {
        int4* d4 = (int4*)&g_deg[base];
        int4 a = d4[0], b = d4[1];
        int d[8] = {a.x, a.y, a.z, a.w, b.x, b.y, b.z, b.w};
        #pragma unroll
        for (int i = 0; i < 8; i++) { v[i] = tot; tot += d[i]; }
        d4[0] = make_int4(0, 0, 0, 0);     // deg stays zeroed for next replay
        d4[1] = make_int4(0, 0, 0, 0);
    } else {
        #pragma unroll
        for (int i = 0; i < 8; i++) v[i] = 0;
    }

    // --- warp scan of thread totals ---
    int inc = tot;
    #pragma unroll
    for (int off = 1; off < 32; off <<= 1) {
        int t = __shfl_up_sync(0xffffffffu, inc, off);
        if (lane >= off) inc += t;
    }
    if (lane == 31) warp_off[wid] = inc;
    int texcl = inc - tot;
    __syncthreads();

    // --- warp 0 scans the 8 warp totals; block total to s_tot ---
    if (wid == 0 && lane < 8) {
        int w = warp_off[lane];
        int wi = w;
        #pragma unroll
        for (int off = 1; off < 8; off <<= 1) {
            int t = __shfl_up_sync(0x000000ffu, wi, off);
            if (lane >= off) wi += t;
        }
        warp_off[lane] = wi - w;
        if (lane == 7) s_tot = wi;
    }
    __syncthreads();

    // --- publish block sum; last-arriving block scans them ---
    if (tid == 0) {
        g_bsum[blockIdx.x] = s_tot;
        __threadfence();
        unsigned old = atomicAdd(&g_ticket1, 1u);
        s_last = (old == (unsigned)(nblocks - 1)) ? 1 : 0;
    }
    __syncthreads();

    if (s_last && wid == 0) {
        int bv = (lane < nblocks) ? g_bsum[lane] : 0;
        int bi = bv;
        #pragma unroll
        for (int off = 1; off < 32; off <<= 1) {
            int t = __shfl_up_sync(0xffffffffu, bi, off);
            if (lane >= off) bi += t;
        }
        if (lane < nblocks) g_boff[lane] = bi - bv;   // exclusive block offsets
        if (lane == 31) g_rowptr[n] = bi;             // grand total
        __threadfence();
        if (lane == 0) atomicExch(&g_scanflag, 1u);
    }

    // --- all blocks wait for boff (25 blocks co-resident: no deadlock) ---
    if (tid == 0) {
        while (atomicAdd(&g_scanflag, 0u) == 0u) { }
    }
    __syncthreads();
    __threadfence();   // acquire: order g_boff reads after flag observation

    int b = g_boff[blockIdx.x] + warp_off[wid] + texcl;
    #pragma unroll
    for (int i = 0; i < 8; i++) {
        int idx = base + i;
        if (idx < n) {
            int val = b + v[i];
            g_rowptr[idx] = val;
            g_cursor[idx] = val;
        }
    }

    // --- departure ticket: last block out resets the flags for next replay ---
    if (tid == 0) {
        __threadfence();
        unsigned old = atomicAdd(&g_ticket2, 1u);
        if (old == (unsigned)(nblocks - 1)) {
            g_ticket1  = 0u;
            g_ticket2  = 0u;
            g_scanflag = 0u;
        }
    }
}

// ---------------- kernel 3: scatter col ids into CSR order ----------------
__global__ void scatter_kernel(const int* __restrict__ rows,
                               const int* __restrict__ cols, int E) {
    int i = blockIdx.x * blockDim.x + threadIdx.x;
    if (i < E) {
        int pos = atomicAdd(&g_cursor[rows[i]], 1);
        g_ecol[pos] = cols[i];
    }
}

// ---------------- kernel 4: fused single-pass segment-softmax attention ----------------
// One warp per destination node. Lane l holds dims [4l, 4l+4); head = l>>3.
// out = (sum_e ea_e * v_e) / (sum_e ea_e + 1e-8)
__global__ void __launch_bounds__(256) attn_kernel(float* __restrict__ out, int n)
{
    int gw   = (blockIdx.x * blockDim.x + threadIdx.x) >> 5;
    int lane = threadIdx.x & 31;
    if (gw >= n) return;

    const float4* Q4 = (const float4*)g_Q;
    const float4* K4 = (const float4*)g_K;
    const float4* V4 = (const float4*)g_V;

    float4 qv = Q4[gw * 32 + lane];
    int beg = g_rowptr[gw];
    int end = g_rowptr[gw + 1];

    float nsum = 0.f;
    float4 acc = make_float4(0.f, 0.f, 0.f, 0.f);
    for (int idx = beg; idx < end; idx++) {
        int c = g_ecol[idx];                      // sequential read, CSR order
        float4 kv = K4[c * 32 + lane];            // two independent row gathers
        float4 vv = V4[c * 32 + lane];
        float p = fmaf(qv.x, kv.x, fmaf(qv.y, kv.y, fmaf(qv.z, kv.z, qv.w * kv.w)));
        p += __shfl_xor_sync(0xffffffffu, p, 1);
        p += __shfl_xor_sync(0xffffffffu, p, 2);
        p += __shfl_xor_sync(0xffffffffu, p, 4);  // full head dot in all 8 lanes of group
        float a  = fminf(fmaxf(p, -10.f), 10.f);
        float ea = __expf(a);
        nsum += ea;
        acc.x = fmaf(ea, vv.x, acc.x);
        acc.y = fmaf(ea, vv.y, acc.y);
        acc.z = fmaf(ea, vv.z, acc.z);
        acc.w = fmaf(ea, vv.w, acc.w);
    }
    float inv = 1.f / (nsum + 1e-8f);
    acc.x *= inv; acc.y *= inv; acc.z *= inv; acc.w *= inv;
    ((float4*)out)[gw * 32 + lane] = acc;
}

// ---------------- launch ----------------
// Order puts attn_kernel at the profiled launch index (3).
extern "C" void kernel_launch(void* const* d_in, const int* in_sizes, int n_in,
                              void* d_out, int out_size) {
    const float* emb  = (const float*)d_in[0];
    const float* qW   = (const float*)d_in[1];
    const float* kW   = (const float*)d_in[2];
    const float* vW   = (const float*)d_in[3];
    const int*   rows = (const int*)d_in[4];
    const int*   cols = (const int*)d_in[5];
    float*       out  = (float*)d_out;

    const int N = in_sizes[0] / DIM;   // 50000
    const int E = in_sizes[4];         // 600000
    const int nsb   = (N + SCAN_TILE - 1) / SCAN_TILE;   // 25 (<= 148: co-resident)
    const int nqkv  = (N + GR - 1) / GR;                 // 3125
    const int nhist = (E + 255) / 256;                   // 2344

    qkvhist_kernel<<<nqkv + nhist, 256>>>(emb, qW, kW, vW, rows, N, nqkv, E); // 0
    scan_kernel<<<nsb, 256>>>(N, nsb);                                        // 1
    scatter_kernel<<<(E + 255) / 256, 256>>>(rows, cols, E);                  // 2
    attn_kernel<<<(N + 7) / 8, 256>>>(out, N);                                // 3 <- profiled
}